// round 3
// baseline (speedup 1.0000x reference)
#include <cuda_runtime.h>
#include <cuda_bf16.h>

#define NATOM 100000
#define MNBR  12
#define AF    64
#define BF    41
#define TWOA  128
#define NM    (NATOM*MNBR)          // 1200000
#define NMF   ((double)NM)
#define NF    ((double)NATOM)
#define EPSBN 1e-5

typedef unsigned long long ull;

// ---------------- scratch (device globals; no allocations) ----------------
__device__ float  d_SW[(size_t)NATOM*TWOA];      // atom @ W[0:64] + bias (51.2 MB)
__device__ float  d_PW[(size_t)NATOM*TWOA];      // atom @ W[64:128]     (51.2 MB)
__device__ float  d_summed[(size_t)NATOM*AF];    // (25.6 MB)
__device__ double d_s1[TWOA], d_q1[TWOA];
__device__ double d_s2[AF],   d_q2[AF];
__device__ float  d_g1[TWOA], d_h1[TWOA];
__device__ float  d_g2[AF],   d_h2[AF];

// ---------------- helpers ----------------
__device__ __forceinline__ void ffma2(ull &d, ull a, ull b) {
    asm("fma.rn.f32x2 %0, %1, %2, %0;" : "+l"(d) : "l"(a), "l"(b));
}
__device__ __forceinline__ ull packdup(float x) {
    ull r; asm("mov.b64 %0, {%1, %1};" : "=l"(r) : "f"(x)); return r;
}
__device__ __forceinline__ float2 unpk(ull v) {
    float2 r; asm("mov.b64 {%0, %1}, %2;" : "=f"(r.x), "=f"(r.y) : "l"(v)); return r;
}
__device__ __forceinline__ float sigmoidf_(float x) {
    return __fdividef(1.0f, 1.0f + __expf(-x));
}
__device__ __forceinline__ float softplusf_(float x) {
    float e = __expf(-fabsf(x));
    return fmaxf(x, 0.0f) + __logf(1.0f + e);
}

// ---------------- zero stats ----------------
__global__ void kZero() {
    int t = threadIdx.x;
    if (t < TWOA) { d_s1[t] = 0.0; d_q1[t] = 0.0; }
    if (t < AF)   { d_s2[t] = 0.0; d_q2[t] = 0.0; }
}

// ---------------- kA: SW = atom@W[0:64,:] + b, PW = atom@W[64:128,:] ----------------
__global__ void __launch_bounds__(256) kA(const float* __restrict__ atom,
                                          const float* __restrict__ W,
                                          const float* __restrict__ bias) {
    __shared__ __align__(16) float at[64][132];   // transposed atom tile [k][a]
    int t = threadIdx.x;
    int aBase = blockIdx.x * 128;
    int aCount = NATOM - aBase; if (aCount > 128) aCount = 128;

    float wreg[64];
    const float* wp = (t < 128) ? (W + t) : (W + 64 * TWOA + (t - 128));
    #pragma unroll
    for (int k = 0; k < 64; k++) wreg[k] = wp[k * TWOA];
    float bj = (t < 128) ? bias[t] : 0.0f;

    for (int idx = t; idx < 128 * 64; idx += 256) {
        int a = idx >> 6, k = idx & 63;
        at[k][a] = (a < aCount) ? atom[(size_t)(aBase + a) * AF + k] : 0.0f;
    }
    __syncthreads();

    float* dst = (t < 128) ? d_SW : d_PW;
    int j = t & 127;

    for (int c = 0; c < 16; c++) {
        int a0 = c * 8;
        ull acc[4] = {0ull, 0ull, 0ull, 0ull};
        #pragma unroll
        for (int k = 0; k < 64; k++) {
            ull wk = packdup(wreg[k]);
            const ull* ap = (const ull*)&at[k][a0];
            ffma2(acc[0], ap[0], wk);
            ffma2(acc[1], ap[1], wk);
            ffma2(acc[2], ap[2], wk);
            ffma2(acc[3], ap[3], wk);
        }
        #pragma unroll
        for (int q = 0; q < 4; q++) {
            float2 v = unpk(acc[q]);
            int a = a0 + 2 * q;
            if (a < aCount)     dst[(size_t)(aBase + a)     * TWOA + j] = v.x + bj;
            if (a + 1 < aCount) dst[(size_t)(aBase + a + 1) * TWOA + j] = v.y + bj;
        }
    }
}

// ==== shared GEMM body: block = 96 rows (8 atoms) x 128 cols, 256 threads ====
// warp w owns atom (blk*8+w); lane owns cols {2l, 2l+1, 64+2l, 64+2l+1}
// acc[p][u]: row-pair p (rows 2p,2p+1 of this atom's 12), u in {cA,cA+1,cB,cB+1}

#define GEMM_PROLOG(bond_, nidx_, W_)                                          \
    int t = threadIdx.x;                                                       \
    int lane = t & 31, w = t >> 5;                                             \
    int rowBase = blockIdx.x * 96;                                             \
    int atom = blockIdx.x * 8 + w;                                             \
    int cA = 2 * lane, cB = 64 + 2 * lane;                                     \
    for (int idx = t; idx < BF * TWOA; idx += 256)                             \
        Ws[idx >> 7][idx & 127] = W_[TWOA * TWOA + idx];                       \
    {                                                                          \
        const float* bsrc = bond_ + (size_t)rowBase * BF;                      \
        for (int idx = t; idx < 96 * BF; idx += 256)                           \
            bT[idx % BF][idx / BF] = bsrc[idx];                                \
    }                                                                          \
    __syncthreads();                                                           \
    int r0 = w * 12;                                                           \
    ull acc[6][4];                                                             \
    _Pragma("unroll")                                                          \
    for (int p = 0; p < 6; p++)                                                \
        _Pragma("unroll")                                                      \
        for (int u = 0; u < 4; u++) acc[p][u] = 0ull;                          \
    _Pragma("unroll")                                                          \
    for (int k = 0; k < BF; k++) {                                             \
        float2 wa = *(const float2*)&Ws[k][cA];                                \
        float2 wb = *(const float2*)&Ws[k][cB];                                \
        ull w0 = packdup(wa.x), w1 = packdup(wa.y);                            \
        ull w2 = packdup(wb.x), w3 = packdup(wb.y);                            \
        const ull* bp = (const ull*)&bT[k][r0];                                \
        _Pragma("unroll")                                                      \
        for (int p = 0; p < 6; p++) {                                          \
            ull bv = bp[p];                                                    \
            ffma2(acc[p][0], bv, w0);                                          \
            ffma2(acc[p][1], bv, w1);                                          \
            ffma2(acc[p][2], bv, w2);                                          \
            ffma2(acc[p][3], bv, w3);                                          \
        }                                                                      \
    }                                                                          \
    const int* ni = nidx_ + atom * MNBR;                                       \
    int4 i0 = *(const int4*)ni;                                                \
    int4 i1 = *(const int4*)(ni + 4);                                          \
    int4 i2 = *(const int4*)(ni + 8);                                          \
    int idx12[12] = {i0.x, i0.y, i0.z, i0.w, i1.x, i1.y, i1.z, i1.w,           \
                     i2.x, i2.y, i2.z, i2.w};                                  \
    float2 swA = *(const float2*)&d_SW[(size_t)atom * TWOA + cA];              \
    float2 swB = *(const float2*)&d_SW[(size_t)atom * TWOA + cB];

// ---------------- kStats: compute gated, accumulate BN1 stats, discard ----------------
__global__ void __launch_bounds__(256) kStats(const float* __restrict__ bond,
                                              const int*   __restrict__ nidx,
                                              const float* __restrict__ W) {
    __shared__ __align__(16) float Ws[BF][TWOA];
    __shared__ __align__(16) float bT[BF][100];
    __shared__ float redS[8][TWOA];
    __shared__ float redQ[8][TWOA];

    GEMM_PROLOG(bond, nidx, W)

    float ls0 = 0, ls1 = 0, ls2 = 0, ls3 = 0;
    float lq0 = 0, lq1 = 0, lq2 = 0, lq3 = 0;
    #pragma unroll
    for (int p = 0; p < 6; p++) {
        float2 aA0 = unpk(acc[p][0]);
        float2 aA1 = unpk(acc[p][1]);
        float2 aB0 = unpk(acc[p][2]);
        float2 aB1 = unpk(acc[p][3]);
        #pragma unroll
        for (int s = 0; s < 2; s++) {
            int gi = idx12[2 * p + s];
            const float* pw = &d_PW[(size_t)gi * TWOA];
            float2 pA = *(const float2*)&pw[cA];
            float2 pB = *(const float2*)&pw[cB];
            float v0 = (s ? aA0.y : aA0.x) + swA.x + pA.x;
            float v1 = (s ? aA1.y : aA1.x) + swA.y + pA.y;
            float v2 = (s ? aB0.y : aB0.x) + swB.x + pB.x;
            float v3 = (s ? aB1.y : aB1.x) + swB.y + pB.y;
            ls0 += v0; lq0 += v0 * v0;
            ls1 += v1; lq1 += v1 * v1;
            ls2 += v2; lq2 += v2 * v2;
            ls3 += v3; lq3 += v3 * v3;
        }
    }
    redS[w][cA] = ls0;  redS[w][cA + 1] = ls1;
    redS[w][cB] = ls2;  redS[w][cB + 1] = ls3;
    redQ[w][cA] = lq0;  redQ[w][cA + 1] = lq1;
    redQ[w][cB] = lq2;  redQ[w][cB + 1] = lq3;
    __syncthreads();
    if (t < TWOA) {
        float s = 0.0f, q = 0.0f;
        #pragma unroll
        for (int w2 = 0; w2 < 8; w2++) { s += redS[w2][t]; q += redQ[w2][t]; }
        atomicAdd(&d_s1[t], (double)s);
        atomicAdd(&d_q1[t], (double)q);
    }
}

// ---------------- fin1 / fin2 ----------------
__global__ void fin1(const float* __restrict__ scale, const float* __restrict__ offset) {
    int j = threadIdx.x;   // 128
    double mean = d_s1[j] / NMF;
    double var  = d_q1[j] / NMF - mean * mean;
    float g = scale[j] * (float)(1.0 / sqrt(var + EPSBN));
    d_g1[j] = g;
    d_h1[j] = offset[j] - (float)mean * g;
}
__global__ void fin2(const float* __restrict__ scale, const float* __restrict__ offset) {
    int j = threadIdx.x;   // 64
    double mean = d_s2[j] / NF;
    double var  = d_q2[j] / NF - mean * mean;
    float g = scale[j] * (float)(1.0 / sqrt(var + EPSBN));
    d_g2[j] = g;
    d_h2[j] = offset[j] - (float)mean * g;
}

// ---------------- kFuse: recompute gated + BN1 affine + sig*softplus + sum_M + BN2 stats ----
__global__ void __launch_bounds__(256) kFuse(const float* __restrict__ bond,
                                             const int*   __restrict__ nidx,
                                             const float* __restrict__ W) {
    __shared__ __align__(16) float Ws[BF][TWOA];
    __shared__ __align__(16) float bT[BF][100];
    __shared__ float rs[8][AF];
    __shared__ float rq[8][AF];

    GEMM_PROLOG(bond, nidx, W)

    float2 G1A = *(const float2*)&d_g1[cA];
    float2 H1A = *(const float2*)&d_h1[cA];
    float2 G1B = *(const float2*)&d_g1[cB];
    float2 H1B = *(const float2*)&d_h1[cB];

    float sum0 = 0.0f, sum1 = 0.0f;
    #pragma unroll
    for (int p = 0; p < 6; p++) {
        float2 aA0 = unpk(acc[p][0]);
        float2 aA1 = unpk(acc[p][1]);
        float2 aB0 = unpk(acc[p][2]);
        float2 aB1 = unpk(acc[p][3]);
        #pragma unroll
        for (int s = 0; s < 2; s++) {
            int gi = idx12[2 * p + s];
            const float* pw = &d_PW[(size_t)gi * TWOA];
            float2 pA = *(const float2*)&pw[cA];
            float2 pB = *(const float2*)&pw[cB];
            float v0 = (s ? aA0.y : aA0.x) + swA.x + pA.x;   // filter col cA
            float v1 = (s ? aA1.y : aA1.x) + swA.y + pA.y;   // filter col cA+1
            float v2 = (s ? aB0.y : aB0.x) + swB.x + pB.x;   // core   col cA (+64)
            float v3 = (s ? aB1.y : aB1.x) + swB.y + pB.y;   // core   col cA+1 (+64)
            float xf0 = v0 * G1A.x + H1A.x;
            float xf1 = v1 * G1A.y + H1A.y;
            float xc0 = v2 * G1B.x + H1B.x;
            float xc1 = v3 * G1B.y + H1B.y;
            sum0 += sigmoidf_(xf0) * softplusf_(xc0);
            sum1 += sigmoidf_(xf1) * softplusf_(xc1);
        }
    }
    float2 sv; sv.x = sum0; sv.y = sum1;
    *(float2*)&d_summed[(size_t)atom * AF + cA] = sv;

    rs[w][cA] = sum0;  rs[w][cA + 1] = sum1;
    rq[w][cA] = sum0 * sum0;  rq[w][cA + 1] = sum1 * sum1;
    __syncthreads();
    if (t < AF) {
        float s = 0.0f, q = 0.0f;
        #pragma unroll
        for (int w2 = 0; w2 < 8; w2++) { s += rs[w2][t]; q += rq[w2][t]; }
        atomicAdd(&d_s2[t], (double)s);
        atomicAdd(&d_q2[t], (double)q);
    }
}

// ---------------- kD: out = softplus(atom + BN2(summed)) ----------------
__global__ void __launch_bounds__(256) kD(const float* __restrict__ atom,
                                          float* __restrict__ out) {
    int i = blockIdx.x * 256 + threadIdx.x;      // grid sized exactly N*AF
    int c = i & (AF - 1);
    float y = d_summed[i] * d_g2[c] + d_h2[c];
    out[i] = softplusf_(atom[i] + y);
}

// ---------------- launch ----------------
extern "C" void kernel_launch(void* const* d_in, const int* in_sizes, int n_in,
                              void* d_out, int out_size) {
    const int*   nidx = (const int*)  d_in[0];   // (N, M) int32
    const float* atom = (const float*)d_in[1];   // (N, 64)
    const float* bond = (const float*)d_in[2];   // (N, M, 41)
    const float* W    = (const float*)d_in[3];   // (169, 128)
    const float* bias = (const float*)d_in[4];   // (128,)
    const float* bn1s = (const float*)d_in[5];
    const float* bn1o = (const float*)d_in[6];
    const float* bn2s = (const float*)d_in[7];
    const float* bn2o = (const float*)d_in[8];
    float* out = (float*)d_out;

    kZero<<<1, 128>>>();
    kA<<<(NATOM + 127) / 128, 256>>>(atom, W, bias);
    kStats<<<NM / 96, 256>>>(bond, nidx, W);
    fin1<<<1, TWOA>>>(bn1s, bn1o);
    kFuse<<<NM / 96, 256>>>(bond, nidx, W);
    fin2<<<1, AF>>>(bn2s, bn2o);
    kD<<<(NATOM * AF) / 256, 256>>>(atom, out);
}